// round 13
// baseline (speedup 1.0000x reference)
#include <cuda_runtime.h>
#include <cuda_fp16.h>
#include <stdint.h>

// ===================== problem dims =====================
// B=8, T=1M, V=257, E=8, C=128, K=S=512, N=64 patches
// GEMM: M=16384 windows, N=256 (c1||c2 interleaved by 32-ch groups), K=4096
// CTA: 128 windows (4 patches, one batch), 256 threads / 8 warps (2 Mwarps x 4 Nwarps)
// Warp tile 64x64, fp32 acc. K-stage = 128 halves (16 byte-positions).
// B: pre-packed per-lane MMA fragments in GMEM -> ld.global.cg -> regs (no smem).
// A: smem 2-stage, emb replicated 8x for conflict-free build gathers, build spread.

#define THREADS    256
#define NITER      32            // K stages of 128 halves (= 16 byte positions)

// smem offsets from 1024-aligned base
#define A_BYTES    32768         // 128 rows x 256B
#define OFF_A      0                         // 2 buffers
#define OFF_EMB    (2 * A_BYTES)             // 65536; emb fp16 x8 copies: 257 * 128B
#define SMEM_ALLOC (OFF_EMB + 257 * 128 + 1024)  // ~99.5KB

// B fragments: [jblock 0..255][nw 0..3][ntp 0..3][lane 0..31][16B] = 2 MB
__device__ __align__(16) unsigned char g_Bfrag[256 * 4 * 4 * 32 * 16];

// ===================== helpers =====================
static __device__ __forceinline__ uint32_t smem_u32(const void* p) {
    uint32_t a;
    asm("{ .reg .u64 t; cvta.to.shared.u64 t, %1; cvt.u32.u64 %0, t; }" : "=r"(a) : "l"(p));
    return a;
}

#define STS128(addr, r0, r1, r2, r3) \
    asm volatile("st.shared.v4.b32 [%0], {%1,%2,%3,%4};" :: "r"(addr), "r"(r0), "r"(r1), "r"(r2), "r"(r3) : "memory")
#define LDS128(r0, r1, r2, r3, addr) \
    asm volatile("ld.shared.v4.b32 {%0,%1,%2,%3}, [%4];" : "=r"(r0), "=r"(r1), "=r"(r2), "=r"(r3) : "r"(addr))

#define LDSM4(r0, r1, r2, r3, addr) \
    asm volatile("ldmatrix.sync.aligned.m8n8.x4.shared.b16 {%0,%1,%2,%3}, [%4];" \
                 : "=r"(r0), "=r"(r1), "=r"(r2), "=r"(r3) : "r"(addr))

#define MMA16816(d, a0, a1, a2, a3, b0, b1) \
    asm volatile("mma.sync.aligned.m16n8k16.row.col.f32.f16.f16.f32 " \
                 "{%0,%1,%2,%3}, {%4,%5,%6,%7}, {%8,%9}, {%0,%1,%2,%3};" \
                 : "+f"((d)[0]), "+f"((d)[1]), "+f"((d)[2]), "+f"((d)[3]) \
                 : "r"(a0), "r"(a1), "r"(a2), "r"(a3), "r"(b0), "r"(b1))

// L2-only 16B load (keeps B out of L1 data arrays)
#define LDG128CG(v, ptr) \
    asm volatile("ld.global.cg.v4.u32 {%0,%1,%2,%3}, [%4];" \
                 : "=r"((v).x), "=r"((v).y), "=r"((v).z), "=r"((v).w) : "l"(ptr))

// ===================== prep: pack B into per-lane MMA fragment order =====================
// For (jblock=stage*8+j, nw, ntp, lane): 16B = {bb0, bb1, bb2, bb3} where
//   n0 = nw*64 + ntp*16 + lane/4 ; n1 = n0 + 8 ; e = (lane%4)*2 ; k = jblock*2
//   bb0 = B[n0][e,e+1 @ k]  bb1 = B[n0][e,e+1 @ k+1]  bb2 = B[n1][..k]  bb3 = B[n1][..k+1]
// Row n: g=n>>5 (even->w1, odd->w2), channel = (g>>1)*32 + (n&31).
// B[n][e @ k] = w[channel*4096 + e*512 + k] as fp16.
__global__ void pack_weights(const float* __restrict__ w1, const float* __restrict__ w2) {
    uint32_t t = blockIdx.x * 256u + threadIdx.x;   // 0..131071, one 16B chunk each
    uint32_t lane = t & 31u;
    uint32_t ntp  = (t >> 5) & 3u;
    uint32_t nw   = (t >> 7) & 3u;
    uint32_t jb   = t >> 9;                         // jblock 0..255
    uint32_t k    = jb * 2u;
    uint32_t e    = (lane & 3u) * 2u;
    uint32_t n0   = nw * 64u + ntp * 16u + (lane >> 2);
    uint4 v;
    #pragma unroll
    for (int half = 0; half < 2; ++half) {
        uint32_t n = n0 + half * 8u;
        uint32_t g = n >> 5;
        const float* w = (g & 1u) ? w2 : w1;
        const float* s = w + ((g >> 1) * 32u + (n & 31u)) * 4096u + e * 512u + k;
        __half2 h0 = __floats2half2_rn(s[0], s[512]);       // (e, e+1) @ k
        __half2 h1 = __floats2half2_rn(s[1], s[513]);       // (e, e+1) @ k+1
        if (half == 0) { v.x = *reinterpret_cast<uint32_t*>(&h0);
                         v.y = *reinterpret_cast<uint32_t*>(&h1); }
        else           { v.z = *reinterpret_cast<uint32_t*>(&h0);
                         v.w = *reinterpret_cast<uint32_t*>(&h1); }
    }
    reinterpret_cast<uint4*>(g_Bfrag)[t] = v;
}

// ===================== main fused kernel =====================
__global__ __launch_bounds__(THREADS, 1)
void malconv_main(const int* __restrict__ x, const float* __restrict__ emb,
                  const float* __restrict__ b1, const float* __restrict__ b2,
                  float* __restrict__ out) {
    extern __shared__ unsigned char smem_raw[];
    const uint32_t AL = (smem_u32(smem_raw) + 1023u) & ~1023u;
    const uint32_t sE = AL + OFF_EMB;

    const int tid  = threadIdx.x;
    const int wid  = tid >> 5;
    const int lane = tid & 31;
    const int mw   = wid >> 2;           // 0..1  (64 rows each)
    const int nw   = wid & 3;            // 0..3  (64 cols each)
    const int m0   = blockIdx.x * 128;   // global window base

    // --- emb -> smem fp16, 8 replicated copies (128B per vocab entry) ---
    for (int v = tid; v < 257; v += THREADS) {
        const float4* e4 = reinterpret_cast<const float4*>(emb + v * 8);
        float4 a = e4[0], bq = e4[1];
        __half2 h0 = __floats2half2_rn(a.x, a.y);
        __half2 h1 = __floats2half2_rn(a.z, a.w);
        __half2 h2 = __floats2half2_rn(bq.x, bq.y);
        __half2 h3 = __floats2half2_rn(bq.z, bq.w);
        uint32_t r0 = *reinterpret_cast<uint32_t*>(&h0);
        uint32_t r1 = *reinterpret_cast<uint32_t*>(&h1);
        uint32_t r2 = *reinterpret_cast<uint32_t*>(&h2);
        uint32_t r3 = *reinterpret_cast<uint32_t*>(&h3);
        #pragma unroll
        for (int r = 0; r < 8; ++r)
            STS128(sE + v * 128 + r * 16, r0, r1, r2, r3);
    }
    __syncthreads();   // emb visible to A-build

    // --- A-build constants: thread builds row bm, units bu0..bu0+7 (one stage = 16 units) ---
    const int bm   = tid >> 1;
    const int bu0  = (tid & 1) * 8;
    const int* xrow = x + (size_t)(m0 + bm) * 512 + bu0;
    const int bmx  = bm & 7;
    const uint32_t lrep = (uint32_t)(lane & 7) * 16;   // replica offset: conflict-free gathers

    // build ONE unit (q_) of this thread's row
    #define BUILD_A1(sA_, xv_, q_) do {                                                 \
        uint32_t e0, e1, e2, e3;                                                        \
        LDS128(e0, e1, e2, e3, sE + (uint32_t)(xv_) * 128 + lrep);                      \
        int cu_ = bu0 + (q_);                                                           \
        uint32_t off_ = (uint32_t)(bm * 256 + (((cu_ & 7) ^ bmx) << 4)                  \
                                   + ((cu_ >> 3) << 7));                                \
        STS128((sA_) + off_, e0, e1, e2, e3);                                           \
    } while (0)

    #define BUILD_A_FULL(sA_, xa_, xb_) do {                                            \
        BUILD_A1(sA_, (xa_).x, 0); BUILD_A1(sA_, (xa_).y, 1);                           \
        BUILD_A1(sA_, (xa_).z, 2); BUILD_A1(sA_, (xa_).w, 3);                           \
        BUILD_A1(sA_, (xb_).x, 4); BUILD_A1(sA_, (xb_).y, 5);                           \
        BUILD_A1(sA_, (xb_).z, 6); BUILD_A1(sA_, (xb_).w, 7);                           \
    } while (0)

    // --- prologue: A(0) build; x(1) prefetch ---
    {
        int4 xa = *reinterpret_cast<const int4*>(xrow + 0);
        int4 xb = *reinterpret_cast<const int4*>(xrow + 4);
        BUILD_A_FULL(AL + OFF_A + 0 * A_BYTES, xa, xb);
    }
    int4 xca = *reinterpret_cast<const int4*>(xrow + 16);
    int4 xcb = *reinterpret_cast<const int4*>(xrow + 20);

    // --- per-thread ldmatrix address constants (A) ---
    const int q4 = lane >> 3;                          // matrix index 0..3
    const int aRowBase = mw * 64 + (lane & 7) + ((q4 & 1) << 3);
    const int aCuHalf  = q4 >> 1;
    const int aXor     = aRowBase & 7;

    // --- B fragment pointer ---
    const unsigned char* bptr = g_Bfrag + ((size_t)nw * 2048) + (size_t)lane * 16;
    // + jblock*8192 + ntp*512

    float acc[4][8][4];
    #pragma unroll
    for (int i = 0; i < 4; ++i)
        #pragma unroll
        for (int j = 0; j < 8; ++j)
            #pragma unroll
            for (int k = 0; k < 4; ++k) acc[i][j][k] = 0.0f;

    // fragment double buffers
    uint32_t afr[2][4][4];     // [buf][mt][reg]
    uint4 bf[2][4];            // [buf][ntp]

    #define OFFA(j_) ((uint32_t)(((((j_) * 2 + aCuHalf) & 7) ^ aXor) << 4) + \
                      ((uint32_t)(((j_) * 2 + aCuHalf) >> 3) << 7))

    #define LOAD_A(buf_, sA_, j_) do {                                                  \
        uint32_t oA_ = OFFA(j_);                                                        \
        _Pragma("unroll")                                                               \
        for (int mt_ = 0; mt_ < 4; ++mt_)                                               \
            LDSM4(afr[buf_][mt_][0], afr[buf_][mt_][1],                                 \
                  afr[buf_][mt_][2], afr[buf_][mt_][3],                                 \
                  (sA_) + (uint32_t)(aRowBase + mt_ * 16) * 256 + oA_);                 \
    } while (0)

    #define MMA_BLOCK(ab_, bb_, ntp_) do {                                              \
        const uint4 bq_ = bf[bb_][ntp_];                                                \
        _Pragma("unroll")                                                               \
        for (int mt_ = 0; mt_ < 4; ++mt_) {                                             \
            MMA16816(acc[mt_][(ntp_) * 2 + 0],                                          \
                     afr[ab_][mt_][0], afr[ab_][mt_][1],                                \
                     afr[ab_][mt_][2], afr[ab_][mt_][3],                                \
                     bq_.x, bq_.y);                                                     \
            MMA16816(acc[mt_][(ntp_) * 2 + 1],                                          \
                     afr[ab_][mt_][0], afr[ab_][mt_][1],                                \
                     afr[ab_][mt_][2], afr[ab_][mt_][3],                                \
                     bq_.z, bq_.w);                                                     \
        }                                                                               \
    } while (0)

    // preload jblock 0 B fragments
    #pragma unroll
    for (int q = 0; q < 4; ++q) LDG128CG(bf[0][q], bptr + q * 512);

    // --- main loop ---
    for (int it = 0; it < NITER; ++it) {
        __syncthreads();          // A(it) visible; stage it-1 A reads all retired

        const uint32_t sA = AL + OFF_A + (it & 1) * A_BYTES;
        const int sNew = it + 1;
        const uint32_t sAn = AL + OFF_A + (sNew & 1) * A_BYTES;
        const bool doNew = (sNew < NITER);

        int4 xna, xnb;            // next-next-stage x (rolled in at stage end)

        // per-iter fragment prologue (A only; B is continuous across stages)
        LOAD_A(0, sA, 0);

        #pragma unroll
        for (int j = 0; j < 8; ++j) {
            const int cb = j & 1;
            const int nb = cb ^ 1;

            // prefetch next j-block's B fragments (clamped at the end)
            {
                int nj = it * 8 + j + 1;
                if (nj > 255) nj = 255;
                const unsigned char* np = bptr + (size_t)nj * 8192;
                #pragma unroll
                for (int q = 0; q < 4; ++q) LDG128CG(bf[nb][q], np + q * 512);
            }

            // spread next-stage A work: 1 build-unit per j
            if (doNew) {
                switch (j) {
                    case 0: BUILD_A1(sAn, xca.x, 0); break;
                    case 1: BUILD_A1(sAn, xca.y, 1); break;
                    case 2: BUILD_A1(sAn, xca.z, 2); break;
                    case 3: BUILD_A1(sAn, xca.w, 3); break;
                    case 4: BUILD_A1(sAn, xcb.x, 4); break;
                    case 5: BUILD_A1(sAn, xcb.y, 5); break;
                    case 6: BUILD_A1(sAn, xcb.z, 6); break;
                    case 7: BUILD_A1(sAn, xcb.w, 7); break;
                }
                if (j == 3 && sNew + 1 < NITER) {
                    xna = *reinterpret_cast<const int4*>(xrow + (sNew + 1) * 16);
                    xnb = *reinterpret_cast<const int4*>(xrow + (sNew + 1) * 16 + 4);
                }
            }

            #pragma unroll
            for (int ntp = 0; ntp < 4; ++ntp) {
                if (ntp == 3 && j < 7) LOAD_A((j + 1) & 1, sA, j + 1);
                MMA_BLOCK(j & 1, cb, ntp);
            }
        }

        if (doNew && sNew + 1 < NITER) { xca = xna; xcb = xnb; }
    }

    // --- epilogue: gate + per-patch max, all in registers ---
    float2 b1v[4], b2v[4];
    {
        const int cb = nw * 32 + 2 * (lane & 3);
        #pragma unroll
        for (int nt = 0; nt < 4; ++nt) {
            b1v[nt] = __ldg(reinterpret_cast<const float2*>(b1 + cb + nt * 8));
            b2v[nt] = __ldg(reinterpret_cast<const float2*>(b2 + cb + nt * 8));
        }
    }
    const int bidx  = blockIdx.x >> 4;
    const int pbase = (blockIdx.x & 15) * 4 + mw * 2;

    #pragma unroll
    for (int pp = 0; pp < 2; ++pp) {
        float* obase = out + (size_t)bidx * 8192 + (size_t)(pbase + pp) * 128;
        #pragma unroll
        for (int nt = 0; nt < 4; ++nt) {
            float gm[2];
            #pragma unroll
            for (int cc = 0; cc < 2; ++cc) {
                float bb1 = (cc == 0) ? b1v[nt].x : b1v[nt].y;
                float bb2 = (cc == 0) ? b2v[nt].x : b2v[nt].y;
                float g = -1e30f;
                #pragma unroll
                for (int mt = pp * 2; mt < pp * 2 + 2; ++mt) {
                    #pragma unroll
                    for (int rh = 0; rh < 2; ++rh) {
                        float c1v = acc[mt][nt][cc + rh * 2] + bb1;
                        float c2v = acc[mt][nt + 4][cc + rh * 2] + bb2;
                        float s = __expf(-c2v);
                        g = fmaxf(g, c1v * __frcp_rn(1.0f + s));
                    }
                }
                #pragma unroll
                for (int off = 4; off <= 16; off <<= 1)
                    g = fmaxf(g, __shfl_xor_sync(0xFFFFFFFFu, g, off));
                gm[cc] = g;
            }
            if ((lane >> 2) == 0) {
                const int ch = nw * 32 + nt * 8 + 2 * (lane & 3);
                *reinterpret_cast<float2*>(obase + ch) = make_float2(gm[0], gm[1]);
            }
        }
    }
}

// ===================== launch =====================
extern "C" void kernel_launch(void* const* d_in, const int* in_sizes, int n_in,
                              void* d_out, int out_size) {
    const int*   x   = (const int*)d_in[0];
    const float* emb = (const float*)d_in[1];
    const float* w1  = (const float*)d_in[2];
    const float* b1  = (const float*)d_in[3];
    const float* w2  = (const float*)d_in[4];
    const float* b2  = (const float*)d_in[5];
    float* out = (float*)d_out;

    cudaFuncSetAttribute(malconv_main, cudaFuncAttributeMaxDynamicSharedMemorySize, SMEM_ALLOC);

    pack_weights<<<512, 256>>>(w1, w2);
    malconv_main<<<128, THREADS, SMEM_ALLOC>>>(x, emb, b1, b2, out);
}

// round 14
// speedup vs baseline: 1.0869x; 1.0869x over previous
#include <cuda_runtime.h>
#include <cuda_fp16.h>
#include <stdint.h>

// ===================== problem dims =====================
// B=8, T=1M, V=257, E=8, C=128, K=S=512, N=64 patches
// GEMM: M=16384 windows, N=256 (c1||c2 interleaved by 32-ch groups), K=4096
// CTA: 128 windows (4 patches, one batch), 256 threads / 8 warps (2 Mwarps x 4 Nwarps)
// Warp tile 64x64, fp32 acc. K-stage = 128 halves (16 byte-positions).
// emb replicated 8x for conflict-free build gathers. Next-stage cp.async lands
// early (j=0..3, commit at j=3); A-builds spread over j=4..7.

#define THREADS    256
#define NITER      32            // K stages of 128 halves (= 16 byte positions)

// smem offsets from 1024-aligned base (2-stage pipeline)
#define A_BYTES    32768         // 128 rows x 256B
#define B_BYTES    65536         // 256 rows x 256B
#define OFF_A      0                         // 2 buffers
#define OFF_B      (2 * A_BYTES)             // 65536, 2 buffers
#define OFF_EMB    (OFF_B + 2 * B_BYTES)     // 196608; emb fp16 x8 copies: 257 * 128B
#define SMEM_ALLOC (OFF_EMB + 257 * 128 + 1024)  // 230528

// packed weights: [32 K-stages][256 rows x 256B, pre-swizzled] = 2 MB
__device__ __align__(16) unsigned char g_Bpack[32 * 65536];

// ===================== helpers =====================
static __device__ __forceinline__ uint32_t smem_u32(const void* p) {
    uint32_t a;
    asm("{ .reg .u64 t; cvta.to.shared.u64 t, %1; cvt.u32.u64 %0, t; }" : "=r"(a) : "l"(p));
    return a;
}

#define STS128(addr, r0, r1, r2, r3) \
    asm volatile("st.shared.v4.b32 [%0], {%1,%2,%3,%4};" :: "r"(addr), "r"(r0), "r"(r1), "r"(r2), "r"(r3) : "memory")
#define LDS128(r0, r1, r2, r3, addr) \
    asm volatile("ld.shared.v4.b32 {%0,%1,%2,%3}, [%4];" : "=r"(r0), "=r"(r1), "=r"(r2), "=r"(r3) : "r"(addr))

#define LDSM4(r0, r1, r2, r3, addr) \
    asm volatile("ldmatrix.sync.aligned.m8n8.x4.shared.b16 {%0,%1,%2,%3}, [%4];" \
                 : "=r"(r0), "=r"(r1), "=r"(r2), "=r"(r3) : "r"(addr))

#define MMA16816(d, a0, a1, a2, a3, b0, b1) \
    asm volatile("mma.sync.aligned.m16n8k16.row.col.f32.f16.f16.f32 " \
                 "{%0,%1,%2,%3}, {%4,%5,%6,%7}, {%8,%9}, {%0,%1,%2,%3};" \
                 : "+f"((d)[0]), "+f"((d)[1]), "+f"((d)[2]), "+f"((d)[3]) \
                 : "r"(a0), "r"(a1), "r"(a2), "r"(a3), "r"(b0), "r"(b1))

#define CP_ASYNC16(dst, src) \
    asm volatile("cp.async.cg.shared.global [%0], [%1], 16;" :: "r"(dst), "l"(src) : "memory")
#define CP_COMMIT()  asm volatile("cp.async.commit_group;" ::: "memory")
#define CP_WAIT0()   asm volatile("cp.async.wait_group 0;" ::: "memory")

// ===================== prep: pack weights fp16, K-major, pre-swizzled =====================
// Stage layout: 256 rows x 256B; unit cu (0..15) of row stored at
//   row*256 + (((cu&7) ^ (row&7))<<4) + ((cu>>3)<<7).
// Unit cu holds e=0..7 (fp16) of byte position k = it*16 + cu.
// Row n: g=n>>5, r=n&31; g even -> w1, g odd -> w2; channel = (g>>1)*32 + r.
__global__ void pack_weights(const float* __restrict__ w1, const float* __restrict__ w2) {
    uint32_t t = blockIdx.x * 256u + threadIdx.x;   // 0..131071, one 16B unit each
    uint32_t it = t >> 12;                          // 4096 units per 64KB stage
    uint32_t swoff = (t & 4095u) << 4;              // byte offset inside stage
    uint32_t row = swoff >> 8;
    uint32_t inrow = swoff & 255u;
    uint32_t cu = ((((inrow >> 4) & 7u) ^ (row & 7u))) | ((inrow >> 7) << 3);
    uint32_t k = it * 16u + cu;                     // byte position 0..511
    uint32_t g = row >> 5, r = row & 31u;
    const float* w = (g & 1u) ? w2 : w1;
    const float* s = w + ((g >> 1) * 32u + r) * 4096u + k;  // + e*512
    __half2 h0 = __floats2half2_rn(s[0],    s[512]);
    __half2 h1 = __floats2half2_rn(s[1024], s[1536]);
    __half2 h2 = __floats2half2_rn(s[2048], s[2560]);
    __half2 h3 = __floats2half2_rn(s[3072], s[3584]);
    uint4 v;
    v.x = *reinterpret_cast<uint32_t*>(&h0);
    v.y = *reinterpret_cast<uint32_t*>(&h1);
    v.z = *reinterpret_cast<uint32_t*>(&h2);
    v.w = *reinterpret_cast<uint32_t*>(&h3);
    reinterpret_cast<uint4*>(g_Bpack)[t] = v;
}

// ===================== main fused kernel =====================
__global__ __launch_bounds__(THREADS, 1)
void malconv_main(const int* __restrict__ x, const float* __restrict__ emb,
                  const float* __restrict__ b1, const float* __restrict__ b2,
                  float* __restrict__ out) {
    extern __shared__ unsigned char smem_raw[];
    const uint32_t AL = (smem_u32(smem_raw) + 1023u) & ~1023u;
    const uint32_t sE = AL + OFF_EMB;

    const int tid  = threadIdx.x;
    const int wid  = tid >> 5;
    const int lane = tid & 31;
    const int mw   = wid >> 2;           // 0..1  (64 rows each)
    const int nw   = wid & 3;            // 0..3  (64 cols each)
    const int m0   = blockIdx.x * 128;   // global window base

    // --- emb -> smem fp16, 8 replicated copies (128B per vocab entry) ---
    for (int v = tid; v < 257; v += THREADS) {
        const float4* e4 = reinterpret_cast<const float4*>(emb + v * 8);
        float4 a = e4[0], bq = e4[1];
        __half2 h0 = __floats2half2_rn(a.x, a.y);
        __half2 h1 = __floats2half2_rn(a.z, a.w);
        __half2 h2 = __floats2half2_rn(bq.x, bq.y);
        __half2 h3 = __floats2half2_rn(bq.z, bq.w);
        uint32_t r0 = *reinterpret_cast<uint32_t*>(&h0);
        uint32_t r1 = *reinterpret_cast<uint32_t*>(&h1);
        uint32_t r2 = *reinterpret_cast<uint32_t*>(&h2);
        uint32_t r3 = *reinterpret_cast<uint32_t*>(&h3);
        #pragma unroll
        for (int r = 0; r < 8; ++r)
            STS128(sE + v * 128 + r * 16, r0, r1, r2, r3);
    }
    __syncthreads();   // emb visible to A-build

    // --- A-build constants: thread builds row bm, units bu0..bu0+7 (one stage = 16 units) ---
    const int bm   = tid >> 1;
    const int bu0  = (tid & 1) * 8;
    const int* xrow = x + (size_t)(m0 + bm) * 512 + bu0;
    const int bmx  = bm & 7;
    const uint32_t lrep = (uint32_t)(lane & 7) * 16;   // replica offset: conflict-free gathers

    // build ONE unit (q_) of this thread's row
    #define BUILD_A1(sA_, xv_, q_) do {                                                 \
        uint32_t e0, e1, e2, e3;                                                        \
        LDS128(e0, e1, e2, e3, sE + (uint32_t)(xv_) * 128 + lrep);                      \
        int cu_ = bu0 + (q_);                                                           \
        uint32_t off_ = (uint32_t)(bm * 256 + (((cu_ & 7) ^ bmx) << 4)                  \
                                   + ((cu_ >> 3) << 7));                                \
        STS128((sA_) + off_, e0, e1, e2, e3);                                           \
    } while (0)

    #define BUILD_A_FULL(sA_, xa_, xb_) do {                                            \
        BUILD_A1(sA_, (xa_).x, 0); BUILD_A1(sA_, (xa_).y, 1);                           \
        BUILD_A1(sA_, (xa_).z, 2); BUILD_A1(sA_, (xa_).w, 3);                           \
        BUILD_A1(sA_, (xb_).x, 4); BUILD_A1(sA_, (xb_).y, 5);                           \
        BUILD_A1(sA_, (xb_).z, 6); BUILD_A1(sA_, (xb_).w, 7);                           \
    } while (0)

    #define ISSUE_B_FULL(stage_, buf_) do {                                             \
        const char* src_ = (const char*)g_Bpack + (size_t)(stage_) * B_BYTES;           \
        uint32_t dst_ = AL + OFF_B + (buf_) * B_BYTES;                                  \
        _Pragma("unroll")                                                               \
        for (int q_ = 0; q_ < 16; ++q_)                                                 \
            CP_ASYNC16(dst_ + (tid + q_ * 256) * 16, src_ + (tid + q_ * 256) * 16);     \
    } while (0)

    // --- prologue: B(0) async; A(0) build; x(1) prefetch ---
    ISSUE_B_FULL(0, 0);
    CP_COMMIT();
    {
        int4 xa = *reinterpret_cast<const int4*>(xrow + 0);
        int4 xb = *reinterpret_cast<const int4*>(xrow + 4);
        BUILD_A_FULL(AL + OFF_A + 0 * A_BYTES, xa, xb);
    }
    int4 xca = *reinterpret_cast<const int4*>(xrow + 16);
    int4 xcb = *reinterpret_cast<const int4*>(xrow + 20);

    // --- per-thread ldmatrix address constants ---
    const int q4 = lane >> 3;                          // matrix index 0..3
    const int aRowBase = mw * 64 + (lane & 7) + ((q4 & 1) << 3);
    const int aCuHalf  = q4 >> 1;
    const int aXor     = aRowBase & 7;
    const int bRowBase = nw * 64 + (lane & 7) + ((lane >> 4) << 3);
    const int bCuHalf  = (lane >> 3) & 1;
    const int bXor     = bRowBase & 7;

    float acc[4][8][4];
    #pragma unroll
    for (int i = 0; i < 4; ++i)
        #pragma unroll
        for (int j = 0; j < 8; ++j)
            #pragma unroll
            for (int k = 0; k < 4; ++k) acc[i][j][k] = 0.0f;

    // fragment double buffers
    uint32_t afr[2][4][4];     // [buf][mt][reg]
    uint32_t bfr[2][4];        // [buf][reg]

    #define OFFA(j_) ((uint32_t)(((((j_) * 2 + aCuHalf) & 7) ^ aXor) << 4) + \
                      ((uint32_t)(((j_) * 2 + aCuHalf) >> 3) << 7))
    #define OFFB(j_) ((uint32_t)(((((j_) * 2 + bCuHalf) & 7) ^ bXor) << 4) + \
                      ((uint32_t)(((j_) * 2 + bCuHalf) >> 3) << 7))

    #define LOAD_A(buf_, sA_, j_) do {                                                  \
        uint32_t oA_ = OFFA(j_);                                                        \
        _Pragma("unroll")                                                               \
        for (int mt_ = 0; mt_ < 4; ++mt_)                                               \
            LDSM4(afr[buf_][mt_][0], afr[buf_][mt_][1],                                 \
                  afr[buf_][mt_][2], afr[buf_][mt_][3],                                 \
                  (sA_) + (uint32_t)(aRowBase + mt_ * 16) * 256 + oA_);                 \
    } while (0)

    #define LOAD_B(buf_, sB_, j_, ntp_) \
        LDSM4(bfr[buf_][0], bfr[buf_][1], bfr[buf_][2], bfr[buf_][3], \
              (sB_) + (uint32_t)(bRowBase + (ntp_) * 16) * 256 + OFFB(j_))

    #define MMA_BLOCK(ab_, bb_, ntp_) do {                                              \
        _Pragma("unroll")                                                               \
        for (int mt_ = 0; mt_ < 4; ++mt_) {                                             \
            MMA16816(acc[mt_][(ntp_) * 2 + 0],                                          \
                     afr[ab_][mt_][0], afr[ab_][mt_][1],                                \
                     afr[ab_][mt_][2], afr[ab_][mt_][3],                                \
                     bfr[bb_][0], bfr[bb_][1]);                                         \
            MMA16816(acc[mt_][(ntp_) * 2 + 1],                                          \
                     afr[ab_][mt_][0], afr[ab_][mt_][1],                                \
                     afr[ab_][mt_][2], afr[ab_][mt_][3],                                \
                     bfr[bb_][2], bfr[bb_][3]);                                         \
        }                                                                               \
    } while (0)

    // --- main loop ---
    for (int it = 0; it < NITER; ++it) {
        CP_WAIT0();               // B(it) resident (committed early last stage -> ~free)
        __syncthreads();          // A(it) visible; stage it-1 reads all retired

        const int bufc = it & 1;
        const uint32_t sA = AL + OFF_A + bufc * A_BYTES;
        const uint32_t sB = AL + OFF_B + bufc * B_BYTES;
        const int sNew = it + 1;
        const int bufn = sNew & 1;
        const uint32_t sAn = AL + OFF_A + bufn * A_BYTES;
        const char* bsrc = (const char*)g_Bpack + (size_t)sNew * B_BYTES;
        const uint32_t bdst = AL + OFF_B + bufn * B_BYTES;
        const bool doNew = (sNew < NITER);

        int4 xna, xnb;            // next-next-stage x (rolled in at stage end)

        // per-iter fragment prologue
        LOAD_A(0, sA, 0);
        LOAD_B(0, sB, 0, 0);

        #pragma unroll
        for (int j = 0; j < 8; ++j) {
            // next-stage staging:
            //   j=0..3: 4 cp.asyncs each, commit at j=3 (lands long before next wait)
            //   j=4..7: 2 A-build units each; x prefetch at j=5
            if (doNew) {
                if (j < 4) {
                    #pragma unroll
                    for (int qq = 0; qq < 4; ++qq)
                        CP_ASYNC16(bdst + (tid + (4 * j + qq) * 256) * 16,
                                   bsrc + (tid + (4 * j + qq) * 256) * 16);
                    if (j == 3) CP_COMMIT();
                } else {
                    switch (j) {
                        case 4: BUILD_A1(sAn, xca.x, 0); BUILD_A1(sAn, xca.y, 1); break;
                        case 5: BUILD_A1(sAn, xca.z, 2); BUILD_A1(sAn, xca.w, 3); break;
                        case 6: BUILD_A1(sAn, xcb.x, 4); BUILD_A1(sAn, xcb.y, 5); break;
                        case 7: BUILD_A1(sAn, xcb.z, 6); BUILD_A1(sAn, xcb.w, 7); break;
                    }
                    if (j == 5 && sNew + 1 < NITER) {
                        xna = *reinterpret_cast<const int4*>(xrow + (sNew + 1) * 16);
                        xnb = *reinterpret_cast<const int4*>(xrow + (sNew + 1) * 16 + 4);
                    }
                }
            }

            #pragma unroll
            for (int ntp = 0; ntp < 4; ++ntp) {
                const int cb = (j * 4 + ntp) & 1;
                const int nb = cb ^ 1;
                if (ntp < 3) {
                    LOAD_B(nb, sB, j, ntp + 1);
                } else if (j < 7) {
                    LOAD_B(nb, sB, j + 1, 0);
                    LOAD_A((j + 1) & 1, sA, j + 1);
                }
                MMA_BLOCK(j & 1, cb, ntp);
            }
        }
        if (!doNew) CP_COMMIT();  // keep group count consistent on the last stage

        if (doNew && sNew + 1 < NITER) { xca = xna; xcb = xnb; }
    }

    // --- epilogue: gate + per-patch max, all in registers ---
    float2 b1v[4], b2v[4];
    {
        const int cb = nw * 32 + 2 * (lane & 3);
        #pragma unroll
        for (int nt = 0; nt < 4; ++nt) {
            b1v[nt] = __ldg(reinterpret_cast<const float2*>(b1 + cb + nt * 8));
            b2v[nt] = __ldg(reinterpret_cast<const float2*>(b2 + cb + nt * 8));
        }
    }
    const int bidx  = blockIdx.x >> 4;
    const int pbase = (blockIdx.x & 15) * 4 + mw * 2;

    #pragma unroll
    for (int pp = 0; pp < 2; ++pp) {
        float* obase = out + (size_t)bidx * 8192 + (size_t)(pbase + pp) * 128;
        #pragma unroll
        for (int nt = 0; nt < 4; ++nt) {
            float gm[2];
            #pragma unroll
            for (int cc = 0; cc < 2; ++cc) {
                float bb1 = (cc == 0) ? b1v[nt].x : b1v[nt].y;
                float bb2 = (cc == 0) ? b2v[nt].x : b2v[nt].y;
                float g = -1e30f;
                #pragma unroll
                for (int mt = pp * 2; mt < pp * 2 + 2; ++mt) {
                    #pragma unroll
                    for (int rh = 0; rh < 2; ++rh) {
                        float c1v = acc[mt][nt][cc + rh * 2] + bb1;
                        float c2v = acc[mt][nt + 4][cc + rh * 2] + bb2;
                        float s = __expf(-c2v);
                        g = fmaxf(g, c1v * __frcp_rn(1.0f + s));
                    }
                }
                #pragma unroll
                for (int off = 4; off <= 16; off <<= 1)
                    g = fmaxf(g, __shfl_xor_sync(0xFFFFFFFFu, g, off));
                gm[cc] = g;
            }
            if ((lane >> 2) == 0) {
                const int ch = nw * 32 + nt * 8 + 2 * (lane & 3);
                *reinterpret_cast<float2*>(obase + ch) = make_float2(gm[0], gm[1]);
            }
        }
    }
}

// ===================== launch =====================
extern "C" void kernel_launch(void* const* d_in, const int* in_sizes, int n_in,
                              void* d_out, int out_size) {
    const int*   x   = (const int*)d_in[0];
    const float* emb = (const float*)d_in[1];
    const float* w1  = (const float*)d_in[2];
    const float* b1  = (const float*)d_in[3];
    const float* w2  = (const float*)d_in[4];
    const float* b2  = (const float*)d_in[5];
    float* out = (float*)d_out;

    cudaFuncSetAttribute(malconv_main, cudaFuncAttributeMaxDynamicSharedMemorySize, SMEM_ALLOC);

    pack_weights<<<512, 256>>>(w1, w2);
    malconv_main<<<128, THREADS, SMEM_ALLOC>>>(x, emb, b1, b2, out);
}